// round 2
// baseline (speedup 1.0000x reference)
#include <cuda_runtime.h>
#include <math.h>

// Problem constants
#define B_    64
#define CIN   16
#define HH    256
#define WW    256
#define COUT  64
#define OH    254
#define OW    254

// Tiling
#define TH     14      // output rows per CTA
#define TW     96      // output cols per CTA
#define PX     6       // pixels per thread along W
#define SROWS  16      // TH + 2 halo
#define SCOLS  98      // TW + 2 halo
#define SPITCH 100     // padded smem row pitch (floats)

#define CB     8       // couts per register block (staged at a time)

#define SMEM_IN_FLOATS   (CIN * SROWS * SPITCH)          // 25600 floats = 102400 B
#define SMEM_W_PAIRS     (CB * CIN * 9)                  // 1152 u64 = 9216 B
#define SMEM_BYTES       (SMEM_IN_FLOATS * 4 + SMEM_W_PAIRS * 8 + COUT * 4)  // 111872 B

typedef unsigned long long u64;

__device__ __forceinline__ u64 pk2(float lo, float hi) {
    u64 r;
    asm("mov.b64 %0, {%1, %2};" : "=l"(r) : "f"(lo), "f"(hi));
    return r;
}
__device__ __forceinline__ float2 upk2(u64 v) {
    float2 f;
    asm("mov.b64 {%0, %1}, %2;" : "=f"(f.x), "=f"(f.y) : "l"(v));
    return f;
}
// Blackwell packed dual fp32 FMA (SASS: FFMA2). Only reachable via PTX.
__device__ __forceinline__ u64 ffma2(u64 a, u64 b, u64 c) {
    u64 d;
    asm("fma.rn.f32x2 %0, %1, %2, %3;" : "=l"(d) : "l"(a), "l"(b), "l"(c));
    return d;
}

extern __shared__ float smem[];

__global__ __launch_bounds__(256, 2)
void conv_min_tanh_kernel(const float* __restrict__ x,
                          const float* __restrict__ w,
                          const float* __restrict__ bias,
                          float* __restrict__ out)
{
    float* sIn = smem;                               // [CIN][SROWS][SPITCH]
    u64*   sW  = (u64*)(smem + SMEM_IN_FLOATS);      // [CB][CIN][9] duplicated pairs (staged per cb)
    float* sB  = (float*)(sW + SMEM_W_PAIRS);        // [COUT]

    const int tx  = threadIdx.x;        // 0..15
    const int ty  = threadIdx.y;        // 0..15
    const int tid = ty * 16 + tx;

    const int tileX = blockIdx.x * TW;
    const int tileY = blockIdx.y * TH;
    const int b     = blockIdx.z;

    if (tid < COUT) sB[tid] = bias[tid];

    // ---- Load input tile (all 16 input channels, with halo, zero-padded OOB) ----
    const float* xb = x + (size_t)b * (CIN * HH * WW);
    for (int i = tid; i < CIN * SROWS * SCOLS; i += 256) {
        int ci  = i / (SROWS * SCOLS);
        int rem = i - ci * (SROWS * SCOLS);
        int r   = rem / SCOLS;
        int c   = rem - r * SCOLS;
        int iy  = tileY + r;
        int ix  = tileX + c;
        float v = 0.0f;
        if (iy < HH && ix < WW)
            v = xb[ci * (HH * WW) + iy * WW + ix];
        sIn[ci * (SROWS * SPITCH) + r * SPITCH + c] = v;
    }

    float mn[PX];
    #pragma unroll
    for (int p = 0; p < PX; p++) mn[p] = __int_as_float(0x7f800000);  // +inf

    #pragma unroll 1
    for (int cb = 0; cb < COUT; cb += CB) {
        // ---- Stage this cout-block's weights as duplicated pairs (9.2 KB) ----
        __syncthreads();   // previous block's readers done (also covers input-load on iter 0)
        const float* wg = w + cb * (CIN * 9);
        for (int i = tid; i < CB * CIN * 9; i += 256) {
            float v = wg[i];
            sW[i] = pk2(v, v);
        }
        __syncthreads();   // stage visible

        u64 acc[CB][3];
        #pragma unroll
        for (int co = 0; co < CB; co++) {
            float bv = sB[cb + co];
            u64 bb = pk2(bv, bv);
            acc[co][0] = bb; acc[co][1] = bb; acc[co][2] = bb;
        }

        #pragma unroll 1
        for (int ci = 0; ci < CIN; ci++) {
            #pragma unroll
            for (int ky = 0; ky < 3; ky++) {
                // 8 consecutive input floats as 4 aligned u64 (24*tx bytes stride:
                // half-warp phases are bank-conflict-free)
                const u64* rp = (const u64*)(sIn + ci * (SROWS * SPITCH)
                                                 + (ty + ky) * SPITCH + tx * PX);
                u64 a0 = rp[0], a1 = rp[1], a2 = rp[2], a3 = rp[3];
                float2 f0 = upk2(a0), f1 = upk2(a1), f2 = upk2(a2), f3 = upk2(a3);
                u64 t0 = pk2(f0.y, f1.x);   // shifted pairs for middle tap
                u64 t1 = pk2(f1.y, f2.x);
                u64 t2 = pk2(f2.y, f3.x);

                const u64* wp = sW + ci * 9 + ky * 3;
                #pragma unroll
                for (int co = 0; co < CB; co++) {
                    u64 w0 = wp[0], w1 = wp[1], w2 = wp[2];   // uniform -> LDS broadcast
                    // taps-outer / acc-inner: same-acc reuse distance 3
                    acc[co][0] = ffma2(w0, a0, acc[co][0]);
                    acc[co][1] = ffma2(w0, a1, acc[co][1]);
                    acc[co][2] = ffma2(w0, a2, acc[co][2]);
                    acc[co][0] = ffma2(w1, t0, acc[co][0]);
                    acc[co][1] = ffma2(w1, t1, acc[co][1]);
                    acc[co][2] = ffma2(w1, t2, acc[co][2]);
                    acc[co][0] = ffma2(w2, a1, acc[co][0]);
                    acc[co][1] = ffma2(w2, a2, acc[co][1]);
                    acc[co][2] = ffma2(w2, a3, acc[co][2]);
                    wp += CIN * 9;   // next cout within the staged block
                }
            }
        }

        #pragma unroll
        for (int co = 0; co < CB; co++) {
            #pragma unroll
            for (int j = 0; j < 3; j++) {
                float2 v = upk2(acc[co][j]);
                mn[2 * j]     = fminf(mn[2 * j],     v.x);
                mn[2 * j + 1] = fminf(mn[2 * j + 1], v.y);
            }
        }
    }

    // ---- Epilogue: double tanh + guarded store ----
    const int oy = tileY + ty;
    if (ty < TH && oy < OH) {
        const int oxb = tileX + tx * PX;
        float* op = out + ((size_t)b * OH + oy) * OW;
        #pragma unroll
        for (int p = 0; p < PX; p++) {
            int ox = oxb + p;
            if (ox < OW) op[ox] = tanhf(tanhf(mn[p]));
        }
    }
}

extern "C" void kernel_launch(void* const* d_in, const int* in_sizes, int n_in,
                              void* d_out, int out_size)
{
    const float* x    = (const float*)d_in[0];   // [64,16,256,256]
    const float* w    = (const float*)d_in[1];   // [64,16,3,3]
    const float* bias = (const float*)d_in[2];   // [64]
    float* out = (float*)d_out;                  // [64,1,254,254]

    cudaFuncSetAttribute(conv_min_tanh_kernel,
                         cudaFuncAttributeMaxDynamicSharedMemorySize, SMEM_BYTES);

    dim3 grid((OW + TW - 1) / TW,   // 3
              (OH + TH - 1) / TH,   // 19
              B_);                  // 64
    dim3 block(16, 16);
    conv_min_tanh_kernel<<<grid, block, SMEM_BYTES>>>(x, w, bias, out);
}

// round 3
// speedup vs baseline: 1.0007x; 1.0007x over previous
#include <cuda_runtime.h>
#include <math.h>

// Problem constants
#define B_    64
#define CIN   16
#define HH    256
#define WW    256
#define COUT  64
#define OH    254
#define OW    254

// Tiling
#define TH     14      // output rows per CTA
#define TW     96      // output cols per CTA
#define PX     6       // pixels per thread along W
#define SROWS  16      // TH + 2 halo
#define SCOLS  98      // TW + 2 halo
#define SPITCH 100     // padded smem row pitch (floats)

#define CB     8       // couts per register block (staged at a time)

#define SMEM_IN_FLOATS   (CIN * SROWS * SPITCH)          // 25600 floats = 102400 B
#define SMEM_W_PAIRS     (CB * CIN * 9)                  // 1152 u64 = 9216 B
#define SMEM_BYTES       (SMEM_IN_FLOATS * 4 + SMEM_W_PAIRS * 8 + COUT * 4)  // 111872 B

typedef unsigned long long u64;

__device__ __forceinline__ u64 pk2(float lo, float hi) {
    u64 r;
    asm("mov.b64 %0, {%1, %2};" : "=l"(r) : "f"(lo), "f"(hi));
    return r;
}
__device__ __forceinline__ float2 upk2(u64 v) {
    float2 f;
    asm("mov.b64 {%0, %1}, %2;" : "=f"(f.x), "=f"(f.y) : "l"(v));
    return f;
}
// Blackwell packed dual fp32 FMA (SASS: FFMA2). Only reachable via PTX.
__device__ __forceinline__ u64 ffma2(u64 a, u64 b, u64 c) {
    u64 d;
    asm("fma.rn.f32x2 %0, %1, %2, %3;" : "=l"(d) : "l"(a), "l"(b), "l"(c));
    return d;
}

extern __shared__ float smem[];

__global__ __launch_bounds__(256, 2)
void conv_min_tanh_kernel(const float* __restrict__ x,
                          const float* __restrict__ w,
                          const float* __restrict__ bias,
                          float* __restrict__ out)
{
    float* sIn = smem;                               // [CIN][SROWS][SPITCH]
    u64*   sW  = (u64*)(smem + SMEM_IN_FLOATS);      // [CB][CIN][9] duplicated pairs (staged per cb)
    float* sB  = (float*)(sW + SMEM_W_PAIRS);        // [COUT]

    const int tx  = threadIdx.x;        // 0..15
    const int ty  = threadIdx.y;        // 0..15
    const int tid = ty * 16 + tx;

    const int tileX = blockIdx.x * TW;
    const int tileY = blockIdx.y * TH;
    const int b     = blockIdx.z;

    if (tid < COUT) sB[tid] = bias[tid];

    // ---- Load input tile (all 16 input channels, with halo, zero-padded OOB) ----
    const float* xb = x + (size_t)b * (CIN * HH * WW);
    for (int i = tid; i < CIN * SROWS * SCOLS; i += 256) {
        int ci  = i / (SROWS * SCOLS);
        int rem = i - ci * (SROWS * SCOLS);
        int r   = rem / SCOLS;
        int c   = rem - r * SCOLS;
        int iy  = tileY + r;
        int ix  = tileX + c;
        float v = 0.0f;
        if (iy < HH && ix < WW)
            v = xb[ci * (HH * WW) + iy * WW + ix];
        sIn[ci * (SROWS * SPITCH) + r * SPITCH + c] = v;
    }

    float mn[PX];
    #pragma unroll
    for (int p = 0; p < PX; p++) mn[p] = __int_as_float(0x7f800000);  // +inf

    #pragma unroll 1
    for (int cb = 0; cb < COUT; cb += CB) {
        // ---- Stage this cout-block's weights as duplicated pairs (9.2 KB) ----
        __syncthreads();   // previous block's readers done (also covers input-load on iter 0)
        const float* wg = w + cb * (CIN * 9);
        for (int i = tid; i < CB * CIN * 9; i += 256) {
            float v = wg[i];
            sW[i] = pk2(v, v);
        }
        __syncthreads();   // stage visible

        u64 acc[CB][3];
        #pragma unroll
        for (int co = 0; co < CB; co++) {
            float bv = sB[cb + co];
            u64 bb = pk2(bv, bv);
            acc[co][0] = bb; acc[co][1] = bb; acc[co][2] = bb;
        }

        #pragma unroll 1
        for (int ci = 0; ci < CIN; ci++) {
            #pragma unroll
            for (int ky = 0; ky < 3; ky++) {
                // 8 consecutive input floats as 4 aligned u64 (24*tx bytes stride:
                // half-warp phases are bank-conflict-free)
                const u64* rp = (const u64*)(sIn + ci * (SROWS * SPITCH)
                                                 + (ty + ky) * SPITCH + tx * PX);
                u64 a0 = rp[0], a1 = rp[1], a2 = rp[2], a3 = rp[3];
                float2 f0 = upk2(a0), f1 = upk2(a1), f2 = upk2(a2), f3 = upk2(a3);
                u64 t0 = pk2(f0.y, f1.x);   // shifted pairs for middle tap
                u64 t1 = pk2(f1.y, f2.x);
                u64 t2 = pk2(f2.y, f3.x);

                const u64* wp = sW + ci * 9 + ky * 3;
                #pragma unroll
                for (int co = 0; co < CB; co++) {
                    u64 w0 = wp[0], w1 = wp[1], w2 = wp[2];   // uniform -> LDS broadcast
                    // taps-outer / acc-inner: same-acc reuse distance 3
                    acc[co][0] = ffma2(w0, a0, acc[co][0]);
                    acc[co][1] = ffma2(w0, a1, acc[co][1]);
                    acc[co][2] = ffma2(w0, a2, acc[co][2]);
                    acc[co][0] = ffma2(w1, t0, acc[co][0]);
                    acc[co][1] = ffma2(w1, t1, acc[co][1]);
                    acc[co][2] = ffma2(w1, t2, acc[co][2]);
                    acc[co][0] = ffma2(w2, a1, acc[co][0]);
                    acc[co][1] = ffma2(w2, a2, acc[co][1]);
                    acc[co][2] = ffma2(w2, a3, acc[co][2]);
                    wp += CIN * 9;   // next cout within the staged block
                }
            }
        }

        #pragma unroll
        for (int co = 0; co < CB; co++) {
            #pragma unroll
            for (int j = 0; j < 3; j++) {
                float2 v = upk2(acc[co][j]);
                mn[2 * j]     = fminf(mn[2 * j],     v.x);
                mn[2 * j + 1] = fminf(mn[2 * j + 1], v.y);
            }
        }
    }

    // ---- Epilogue: double tanh + guarded store ----
    const int oy = tileY + ty;
    if (ty < TH && oy < OH) {
        const int oxb = tileX + tx * PX;
        float* op = out + ((size_t)b * OH + oy) * OW;
        #pragma unroll
        for (int p = 0; p < PX; p++) {
            int ox = oxb + p;
            if (ox < OW) op[ox] = tanhf(tanhf(mn[p]));
        }
    }
}

extern "C" void kernel_launch(void* const* d_in, const int* in_sizes, int n_in,
                              void* d_out, int out_size)
{
    const float* x    = (const float*)d_in[0];   // [64,16,256,256]
    const float* w    = (const float*)d_in[1];   // [64,16,3,3]
    const float* bias = (const float*)d_in[2];   // [64]
    float* out = (float*)d_out;                  // [64,1,254,254]

    cudaFuncSetAttribute(conv_min_tanh_kernel,
                         cudaFuncAttributeMaxDynamicSharedMemorySize, SMEM_BYTES);

    dim3 grid((OW + TW - 1) / TW,   // 3
              (OH + TH - 1) / TH,   // 19
              B_);                  // 64
    dim3 block(16, 16);
    conv_min_tanh_kernel<<<grid, block, SMEM_BYTES>>>(x, w, bias, out);
}

// round 5
// speedup vs baseline: 6.4284x; 6.4241x over previous
#include <cuda_runtime.h>
#include <cuda_bf16.h>
#include <math.h>
#include <stdint.h>

// ---------------- problem constants ----------------
#define OHW         254
#define STRIP_OROWS 16
#define STRIPS      16
#define OCHUNKS     32          // output pixel chunks of 128 per strip
#define ICHUNKS     36          // + 4 halo chunks (2 extra input rows)
#define NSLOTS      5
#define APITCH      112         // bytes per A row (96 data + 16 pad; conflict-free)
#define SLOT_BYTES  (128 * APITCH)      // 14336
#define OFF_RED     0                    // 256 floats
#define OFF_A       1024
#define SMEM_BYTES  (OFF_A + NSLOTS * SLOT_BYTES)   // 72704

__device__ __forceinline__ uint32_t smem_u32(const void* p) {
    uint32_t a;
    asm("{ .reg .u64 t; cvta.to.shared.u64 t, %1; cvt.u32.u64 %0, t; }"
        : "=r"(a) : "l"(p));
    return a;
}
__device__ __forceinline__ void ldmatrix_x4(uint32_t& a0, uint32_t& a1,
                                            uint32_t& a2, uint32_t& a3,
                                            uint32_t addr) {
    asm volatile("ldmatrix.sync.aligned.m8n8.x4.shared.b16 {%0,%1,%2,%3}, [%4];"
                 : "=r"(a0), "=r"(a1), "=r"(a2), "=r"(a3) : "r"(addr));
}
__device__ __forceinline__ void mma_bf16(float* c, uint32_t a0, uint32_t a1,
                                         uint32_t a2, uint32_t a3,
                                         uint32_t b0, uint32_t b1) {
    asm volatile(
        "mma.sync.aligned.m16n8k16.row.col.f32.bf16.bf16.f32 "
        "{%0,%1,%2,%3}, {%4,%5,%6,%7}, {%8,%9}, {%0,%1,%2,%3};"
        : "+f"(c[0]), "+f"(c[1]), "+f"(c[2]), "+f"(c[3])
        : "r"(a0), "r"(a1), "r"(a2), "r"(a3), "r"(b0), "r"(b1));
}
__device__ __forceinline__ uint32_t pkbf(float lo, float hi) {
    __nv_bfloat162 t = __float22bfloat162_rn(make_float2(lo, hi));
    return *reinterpret_cast<uint32_t*>(&t);
}

extern __shared__ char smem[];

// Build one 128-row A chunk: row = input pixel (iy, ix), K = ci*3+kw (48 bf16).
// 2 threads/row: half h -> ci 8h..8h+7 -> bytes [h*48, h*48+48).
__device__ __forceinline__ void build_chunk(int ch, int oy0,
                                            const float* __restrict__ xb, int tid) {
    const int r  = tid & 127;
    const int h  = tid >> 7;
    const int p  = ch * 128 + r;
    const int iy = oy0 + (p >> 8);
    const int ix = p & 255;

    float v[24];
    if (iy < 256) {
        const float* xp = xb + ((size_t)(h * 8) << 16) + iy * 256 + ix;
        #pragma unroll
        for (int c8 = 0; c8 < 8; c8++) {
            #pragma unroll
            for (int kw = 0; kw < 3; kw++)
                v[c8 * 3 + kw] = (ix + kw < 256) ? __ldg(xp + (c8 << 16) + kw) : 0.0f;
        }
    } else {
        #pragma unroll
        for (int e = 0; e < 24; e++) v[e] = 0.0f;
    }

    uint32_t u[12];
    #pragma unroll
    for (int j = 0; j < 12; j++) u[j] = pkbf(v[2 * j], v[2 * j + 1]);

    char* base = smem + OFF_A + (ch % NSLOTS) * SLOT_BYTES + r * APITCH + h * 48;
    *reinterpret_cast<uint4*>(base)      = make_uint4(u[0], u[1], u[2],  u[3]);
    *reinterpret_cast<uint4*>(base + 16) = make_uint4(u[4], u[5], u[6],  u[7]);
    *reinterpret_cast<uint4*>(base + 32) = make_uint4(u[8], u[9], u[10], u[11]);
}

__global__ __launch_bounds__(256, 1)
void conv_mma_kernel(const float* __restrict__ x, const float* __restrict__ w,
                     const float* __restrict__ bias, float* __restrict__ out)
{
    const int tid  = threadIdx.x;
    const int warp = tid >> 5;
    const int lane = tid & 31;
    const int g    = lane >> 2;       // fragment group (row / n index)
    const int q    = lane & 3;        // thread-in-group (k / col pairs)
    const int nh   = warp & 1;        // n-half: couts [nh*32, nh*32+32)
    const int mq   = warp >> 1;       // m-quarter: rows [mq*32, mq*32+32) in chunk

    const int strip = blockIdx.x;
    const int b     = blockIdx.y;
    const int oy0   = strip * STRIP_OROWS;
    const uint32_t sbase = smem_u32(smem);
    float* red = (float*)(smem + OFF_RED);

    // ---- B fragments in registers, constant for the whole kernel ----
    // b0 = {B[k0][n], B[k0+1][n]}, b1 = {B[k0+8][n], B[k0+9][n]},
    // k0 = s*16 + 2q, n = nh*32 + nt*8 + g.  k = ci*3+kw -> w[n*144 + (k/3)*9 + kh*3 + k%3]
    uint32_t breg[3][3][4][2];
    #pragma unroll
    for (int kh = 0; kh < 3; kh++) {
        #pragma unroll
        for (int s = 0; s < 3; s++) {
            #pragma unroll
            for (int nt = 0; nt < 4; nt++) {
                const int n  = nh * 32 + nt * 8 + g;
                const int k0 = s * 16 + 2 * q;
                const float* wn = w + n * 144 + kh * 3;
                float f0 = __ldg(wn + ((k0    ) / 3) * 9 + (k0    ) % 3);
                float f1 = __ldg(wn + ((k0 + 1) / 3) * 9 + (k0 + 1) % 3);
                float f2 = __ldg(wn + ((k0 + 8) / 3) * 9 + (k0 + 8) % 3);
                float f3 = __ldg(wn + ((k0 + 9) / 3) * 9 + (k0 + 9) % 3);
                breg[kh][s][nt][0] = pkbf(f0, f1);
                breg[kh][s][nt][1] = pkbf(f2, f3);
            }
        }
    }
    // bias for this thread's C columns: cout = nh*32 + nt*8 + 2q (+1)
    float blo[4], bhi[4];
    #pragma unroll
    for (int nt = 0; nt < 4; nt++) {
        blo[nt] = __ldg(bias + nh * 32 + nt * 8 + 2 * q);
        bhi[nt] = __ldg(bias + nh * 32 + nt * 8 + 2 * q + 1);
    }

    const float* xb = x + ((size_t)b << 20);   // b * 16 * 65536

    // ---- prologue: A chunks 0..3 ----
    #pragma unroll 1
    for (int pc = 0; pc < 4; pc++) build_chunk(pc, oy0, xb, tid);

    // ---- main pipeline ----
    #pragma unroll 1
    for (int i = 0; i < OCHUNKS; i++) {
        build_chunk(i + 4, oy0, xb, tid);      // chunks 4..35
        __syncthreads();                       // build -> compute

        float acc[2][4][4];
        #pragma unroll
        for (int mt = 0; mt < 2; mt++)
            #pragma unroll
            for (int nt = 0; nt < 4; nt++) {
                acc[mt][nt][0] = blo[nt]; acc[mt][nt][1] = bhi[nt];
                acc[mt][nt][2] = blo[nt]; acc[mt][nt][3] = bhi[nt];
            }

        #pragma unroll
        for (int kh = 0; kh < 3; kh++) {
            const uint32_t slotbase = sbase + OFF_A
                                    + (uint32_t)(((i + 2 * kh) % NSLOTS) * SLOT_BYTES);
            #pragma unroll
            for (int s = 0; s < 3; s++) {
                #pragma unroll
                for (int mt = 0; mt < 2; mt++) {
                    uint32_t addr = slotbase
                                  + (mq * 32 + mt * 16 + (lane & 15)) * APITCH
                                  + ((lane >> 4) << 4) + s * 32;
                    uint32_t a0, a1, a2, a3;
                    ldmatrix_x4(a0, a1, a2, a3, addr);
                    #pragma unroll
                    for (int nt = 0; nt < 4; nt++)
                        mma_bf16(acc[mt][nt], a0, a1, a2, a3,
                                 breg[kh][s][nt][0], breg[kh][s][nt][1]);
                }
            }
        }

        // ---- epilogue: min over couts -> tanh(tanh) -> store ----
        // rows (in chunk): mq*32 + {g, g+8, g+16, g+24}
        float m[4];
        #pragma unroll
        for (int mt = 0; mt < 2; mt++) {
            float lo = acc[mt][0][0], hi = acc[mt][0][2];
            lo = fminf(lo, acc[mt][0][1]); hi = fminf(hi, acc[mt][0][3]);
            #pragma unroll
            for (int nt = 1; nt < 4; nt++) {
                lo = fminf(lo, fminf(acc[mt][nt][0], acc[mt][nt][1]));
                hi = fminf(hi, fminf(acc[mt][nt][2], acc[mt][nt][3]));
            }
            m[mt * 2]     = lo;   // row mq*32 + mt*16 + g
            m[mt * 2 + 1] = hi;   // row mq*32 + mt*16 + g + 8
        }
        #pragma unroll
        for (int j = 0; j < 4; j++) {
            m[j] = fminf(m[j], __shfl_xor_sync(0xFFFFFFFFu, m[j], 1));
            m[j] = fminf(m[j], __shfl_xor_sync(0xFFFFFFFFu, m[j], 2));
        }
        if (q == 0) {
            const int rb = mq * 32 + g;
            red[(rb     ) * 2 + nh] = m[0];
            red[(rb +  8) * 2 + nh] = m[1];
            red[(rb + 16) * 2 + nh] = m[2];
            red[(rb + 24) * 2 + nh] = m[3];
        }
        __syncthreads();                       // red writes -> combine

        if (tid < 128) {
            float mm = fminf(red[2 * tid], red[2 * tid + 1]);
            float y  = tanhf(tanhf(mm));
            const int p  = i * 128 + tid;
            const int oy = oy0 + (p >> 8);
            const int ox = p & 255;
            if (ox < OHW && oy < OHW)
                out[((size_t)b * OHW + oy) * OHW + ox] = y;
        }
        // next iteration's post-build __syncthreads separates these red reads
        // from the next red writes, and compute(i) from build(i+5) slot reuse.
    }
}

extern "C" void kernel_launch(void* const* d_in, const int* in_sizes, int n_in,
                              void* d_out, int out_size)
{
    const float* x    = (const float*)d_in[0];   // [64,16,256,256]
    const float* w    = (const float*)d_in[1];   // [64,16,3,3]
    const float* bias = (const float*)d_in[2];   // [64]
    float* out = (float*)d_out;                  // [64,1,254,254]

    cudaFuncSetAttribute(conv_mma_kernel,
                         cudaFuncAttributeMaxDynamicSharedMemorySize, SMEM_BYTES);

    dim3 grid(STRIPS, 64);   // 16 strips x 64 images = 1024 CTAs
    conv_mma_kernel<<<grid, 256, SMEM_BYTES>>>(x, w, bias, out);
}

// round 6
// speedup vs baseline: 9.2892x; 1.4450x over previous
#include <cuda_runtime.h>
#include <cuda_bf16.h>
#include <math.h>
#include <stdint.h>

// ---------------- problem constants ----------------
#define OHW         254
#define STRIP_OROWS 16
#define STRIPS      16
#define OCHUNKS     32          // output pixel chunks of 128 per strip
#define NSLOTS      5
#define APITCH      112         // bytes per A/B row (96 data + 16 pad; conflict-free)
#define SLOT_BYTES  (128 * APITCH)       // 14336
#define BKH_BYTES   (64 * APITCH)        // 7168 per kh
#define OFF_RED     0                    // 256 floats
#define OFF_B       1024                 // 3 * 7168 = 21504
#define OFF_A       (OFF_B + 3 * BKH_BYTES)          // 22528
#define SMEM_BYTES  (OFF_A + NSLOTS * SLOT_BYTES)    // 94208

__device__ __forceinline__ uint32_t smem_u32(const void* p) {
    uint32_t a;
    asm("{ .reg .u64 t; cvta.to.shared.u64 t, %1; cvt.u32.u64 %0, t; }"
        : "=r"(a) : "l"(p));
    return a;
}
__device__ __forceinline__ void ldmatrix_x4(uint32_t& a0, uint32_t& a1,
                                            uint32_t& a2, uint32_t& a3,
                                            uint32_t addr) {
    asm volatile("ldmatrix.sync.aligned.m8n8.x4.shared.b16 {%0,%1,%2,%3}, [%4];"
                 : "=r"(a0), "=r"(a1), "=r"(a2), "=r"(a3) : "r"(addr));
}
__device__ __forceinline__ void mma_bf16(float* c, uint32_t a0, uint32_t a1,
                                         uint32_t a2, uint32_t a3,
                                         uint32_t b0, uint32_t b1) {
    asm volatile(
        "mma.sync.aligned.m16n8k16.row.col.f32.bf16.bf16.f32 "
        "{%0,%1,%2,%3}, {%4,%5,%6,%7}, {%8,%9}, {%0,%1,%2,%3};"
        : "+f"(c[0]), "+f"(c[1]), "+f"(c[2]), "+f"(c[3])
        : "r"(a0), "r"(a1), "r"(a2), "r"(a3), "r"(b0), "r"(b1));
}
__device__ __forceinline__ uint32_t pkbf(float lo, float hi) {
    __nv_bfloat162 t = __float22bfloat162_rn(make_float2(lo, hi));
    return *reinterpret_cast<uint32_t*>(&t);
}

extern __shared__ char smem[];

// Build one 128-row A chunk: row = input pixel (iy, ix), K = ci*3+kw (48 bf16).
// 2 threads/row: half h -> ci 8h..8h+7 -> bytes [h*48, h*48+48).
__device__ __forceinline__ void build_chunk(int ch, int oy0,
                                            const float* __restrict__ xb, int tid) {
    const int r  = tid & 127;
    const int h  = tid >> 7;
    const int p  = ch * 128 + r;
    const int iy = oy0 + (p >> 8);
    const int ix = p & 255;

    float v[24];
    if (iy < 256) {
        const float* xp = xb + ((size_t)(h * 8) << 16) + iy * 256 + ix;
        #pragma unroll
        for (int c8 = 0; c8 < 8; c8++) {
            #pragma unroll
            for (int kw = 0; kw < 3; kw++)
                v[c8 * 3 + kw] = (ix + kw < 256) ? __ldg(xp + (c8 << 16) + kw) : 0.0f;
        }
    } else {
        #pragma unroll
        for (int e = 0; e < 24; e++) v[e] = 0.0f;
    }

    uint32_t u[12];
    #pragma unroll
    for (int j = 0; j < 12; j++) u[j] = pkbf(v[2 * j], v[2 * j + 1]);

    char* base = smem + OFF_A + (ch % NSLOTS) * SLOT_BYTES + r * APITCH + h * 48;
    *reinterpret_cast<uint4*>(base)      = make_uint4(u[0], u[1], u[2],  u[3]);
    *reinterpret_cast<uint4*>(base + 16) = make_uint4(u[4], u[5], u[6],  u[7]);
    *reinterpret_cast<uint4*>(base + 32) = make_uint4(u[8], u[9], u[10], u[11]);
}

__global__ __launch_bounds__(256, 2)
void conv_mma_kernel(const float* __restrict__ x, const float* __restrict__ w,
                     const float* __restrict__ bias, float* __restrict__ out)
{
    const int tid  = threadIdx.x;
    const int warp = tid >> 5;
    const int lane = tid & 31;
    const int g    = lane >> 2;       // fragment group
    const int q    = lane & 3;        // thread-in-group
    const int nh   = warp & 1;        // n-half: couts [nh*32, nh*32+32)
    const int mq   = warp >> 1;       // m-quarter: rows [mq*32, mq*32+32)

    const int strip = blockIdx.x;
    const int b     = blockIdx.y;
    const int oy0   = strip * STRIP_OROWS;
    const uint32_t sbase = smem_u32(smem);
    float* red = (float*)(smem + OFF_RED);

    // ---- B into smem, once: rows = cout n (K-major, 48 bf16, per-kh block) ----
    // B[k][n] = w[n*144 + (k/3)*9 + kh*3 + k%3]
    for (int idx = tid; idx < 3 * 64 * 48; idx += 256) {
        const int kh = idx / (64 * 48);
        const int rm = idx % (64 * 48);
        const int n  = rm / 48;
        const int k  = rm % 48;
        const float val = __ldg(w + n * 144 + (k / 3) * 9 + kh * 3 + (k % 3));
        *reinterpret_cast<__nv_bfloat16*>(smem + OFF_B + kh * BKH_BYTES
                                          + n * APITCH + k * 2) = __float2bfloat16(val);
    }

    // bias for this thread's C columns: cout = nh*32 + nt*8 + 2q (+1)
    float blo[4], bhi[4];
    #pragma unroll
    for (int nt = 0; nt < 4; nt++) {
        blo[nt] = __ldg(bias + nh * 32 + nt * 8 + 2 * q);
        bhi[nt] = __ldg(bias + nh * 32 + nt * 8 + 2 * q + 1);
    }

    const float* xb = x + ((size_t)b << 20);   // b * 16 * 65536

    // ldmatrix lane addresses (constant offsets within tiles)
    // A: rows 16 (lane&15), col halves (lane>>4)
    const uint32_t a_row_off = (uint32_t)((lane & 15) * APITCH + ((lane >> 4) << 4));
    // B: tile t = lane>>3 -> nt-subpair t>>1, k-half t&1; rows lane&7
    const uint32_t b_lane_off = (uint32_t)((nh * 32 + ((lane >> 3) >> 1) * 8 + (lane & 7)) * APITCH
                                           + (((lane >> 3) & 1) << 4));

    // ---- prologue: A chunks 0..3 ----
    #pragma unroll 1
    for (int pc = 0; pc < 4; pc++) build_chunk(pc, oy0, xb, tid);

    // ---- main pipeline ----
    #pragma unroll 1
    for (int i = 0; i < OCHUNKS; i++) {
        build_chunk(i + 4, oy0, xb, tid);      // chunks 4..35
        __syncthreads();                       // build + (iter0) B-init -> compute

        float acc[2][4][4];
        #pragma unroll
        for (int mt = 0; mt < 2; mt++)
            #pragma unroll
            for (int nt = 0; nt < 4; nt++) {
                acc[mt][nt][0] = blo[nt]; acc[mt][nt][1] = bhi[nt];
                acc[mt][nt][2] = blo[nt]; acc[mt][nt][3] = bhi[nt];
            }

        #pragma unroll
        for (int kh = 0; kh < 3; kh++) {
            const uint32_t slotbase = sbase + OFF_A
                                    + (uint32_t)(((i + 2 * kh) % NSLOTS) * SLOT_BYTES);
            const uint32_t bbase = sbase + OFF_B + kh * BKH_BYTES + b_lane_off;
            #pragma unroll
            for (int s = 0; s < 3; s++) {
                // B fragments for 4 n-tiles: two x4 loads (nt 0,1 then nt 2,3)
                uint32_t bf[8];
                ldmatrix_x4(bf[0], bf[1], bf[2], bf[3], bbase + s * 32);
                ldmatrix_x4(bf[4], bf[5], bf[6], bf[7], bbase + 16 * APITCH + s * 32);
                #pragma unroll
                for (int mt = 0; mt < 2; mt++) {
                    uint32_t addr = slotbase + (uint32_t)((mq * 32 + mt * 16) * APITCH)
                                  + a_row_off + s * 32;
                    uint32_t a0, a1, a2, a3;
                    ldmatrix_x4(a0, a1, a2, a3, addr);
                    #pragma unroll
                    for (int nt = 0; nt < 4; nt++)
                        mma_bf16(acc[mt][nt], a0, a1, a2, a3,
                                 bf[nt * 2], bf[nt * 2 + 1]);
                }
            }
        }

        // ---- epilogue: min over couts -> tanh(tanh) -> store ----
        float m[4];
        #pragma unroll
        for (int mt = 0; mt < 2; mt++) {
            float lo = fminf(acc[mt][0][0], acc[mt][0][1]);
            float hi = fminf(acc[mt][0][2], acc[mt][0][3]);
            #pragma unroll
            for (int nt = 1; nt < 4; nt++) {
                lo = fminf(lo, fminf(acc[mt][nt][0], acc[mt][nt][1]));
                hi = fminf(hi, fminf(acc[mt][nt][2], acc[mt][nt][3]));
            }
            m[mt * 2]     = lo;   // row mq*32 + mt*16 + g
            m[mt * 2 + 1] = hi;   // row mq*32 + mt*16 + g + 8
        }
        #pragma unroll
        for (int j = 0; j < 4; j++) {
            m[j] = fminf(m[j], __shfl_xor_sync(0xFFFFFFFFu, m[j], 1));
            m[j] = fminf(m[j], __shfl_xor_sync(0xFFFFFFFFu, m[j], 2));
        }
        if (q == 0) {
            const int rb = mq * 32 + g;
            red[(rb     ) * 2 + nh] = m[0];
            red[(rb +  8) * 2 + nh] = m[1];
            red[(rb + 16) * 2 + nh] = m[2];
            red[(rb + 24) * 2 + nh] = m[3];
        }
        __syncthreads();                       // red writes -> combine

        if (tid < 128) {
            float mm = fminf(red[2 * tid], red[2 * tid + 1]);
            float y  = tanhf(tanhf(mm));
            const int p  = i * 128 + tid;
            const int oy = oy0 + (p >> 8);
            const int ox = p & 255;
            if (ox < OHW && oy < OHW)
                out[((size_t)b * OHW + oy) * OHW + ox] = y;
        }
        // next iteration's post-build __syncthreads separates these red reads
        // from the next red writes, and compute(i) from build(i+5) slot reuse.
    }
}

extern "C" void kernel_launch(void* const* d_in, const int* in_sizes, int n_in,
                              void* d_out, int out_size)
{
    const float* x    = (const float*)d_in[0];   // [64,16,256,256]
    const float* w    = (const float*)d_in[1];   // [64,16,3,3]
    const float* bias = (const float*)d_in[2];   // [64]
    float* out = (float*)d_out;                  // [64,1,254,254]

    cudaFuncSetAttribute(conv_mma_kernel,
                         cudaFuncAttributeMaxDynamicSharedMemorySize, SMEM_BYTES);

    dim3 grid(STRIPS, 64);   // 16 strips x 64 images = 1024 CTAs
    conv_mma_kernel<<<grid, 256, SMEM_BYTES>>>(x, w, bias, out);
}